// round 5
// baseline (speedup 1.0000x reference)
#include <cuda_runtime.h>
#include <cstdint>

#define BB 32
#define TT 256
#define DD 384
#define MAXLEN 2048
#define TILE 32          // frames per copy-block
#define NTHREADS 256
#define VEC (DD/4)       // 96 float4 per row

// frame -> token index, per (batch, frame). -1 = beyond mel_len (zero fill).
__device__ int g_fidx[BB * MAXLEN];

// ---------------- Kernel 1: scan + searchsorted (one block per batch) ----------
__global__ __launch_bounds__(NTHREADS)
void lr_index_kernel(const int* __restrict__ dur32,
                     float* __restrict__ mel_f32,
                     long long* __restrict__ mel_i64)
{
    __shared__ int csum[TT];
    const int b   = blockIdx.x;
    const int tid = threadIdx.x;

    // dtype layout detection (int32 vs int64 little-endian): durations are in
    // [0,8), so if the buffer is int64 every odd 32-bit word of the first 512
    // words is 0. All blocks probe the same region -> consistent decision.
    int probe = dur32[2 * tid + 1];
    const int is64 = (__syncthreads_or(probe) == 0);

    csum[tid] = is64 ? dur32[(b * TT + tid) * 2] : dur32[b * TT + tid];
    __syncthreads();
    #pragma unroll
    for (int off = 1; off < TT; off <<= 1) {
        int add = (tid >= off) ? csum[tid - off] : 0;
        __syncthreads();
        csum[tid] += add;
        __syncthreads();
    }
    const int mel_len = csum[TT - 1];

    // 8 frames per thread; searchsorted-right over 257-value answer space -> 9 iters
    #pragma unroll
    for (int r = 0; r < MAXLEN / NTHREADS; r++) {
        const int t = r * NTHREADS + tid;
        int v;
        if (t >= mel_len) {
            v = -1;
        } else {
            int lo = 0, hi = TT;
            #pragma unroll
            for (int s = 0; s < 9; s++) {
                int mid = (lo + hi) >> 1;
                if (csum[mid] > t) hi = mid; else lo = mid + 1;
            }
            v = (lo < TT - 1) ? lo : (TT - 1);
        }
        g_fidx[b * MAXLEN + t] = v;
    }

    if (tid == 0) {
        if (mel_f32) mel_f32[b] = (float)mel_len;
        if (mel_i64) mel_i64[b] = (long long)mel_len;
    }
}

// ---------------- Kernel 2: pure streaming gather/expand -----------------------
// Each block: 32 frames * 384 floats = 48KB out. Thread layout: tid = f8*32 + kk
// where kk in [0,32) indexes vec4-lane groups, f8 in [0,8) indexes frame octets.
// Each thread does 4 frames? Simpler: j = i*256+tid, f = j>>5 mapping with
// VEC=96 not power of two -- instead use frame-major fixed mapping:
// thread handles frames f0 = tid/8 (32 values? no). Keep it simple and exact:
// 3072 vec4s, 256 threads, 12 each; f = j/96 computed by compiler (96 = 32*3,
// strength-reduced). We instead iterate f in [0,32), k = tid%96? 256 threads /
// 96 lanes is awkward; use the proven j-loop but precompute f,k incrementally.
__global__ __launch_bounds__(NTHREADS)
void lr_copy_kernel(const float* __restrict__ x,
                    float* __restrict__ out)
{
    __shared__ int fidx[TILE];

    const int b     = blockIdx.y;
    const int tile0 = blockIdx.x * TILE;
    const int tid   = threadIdx.x;

    if (tid < TILE)
        fidx[tid] = g_fidx[b * MAXLEN + tile0 + tid];
    __syncthreads();

    const float4* __restrict__ x4 = (const float4*)(x + (long)b * TT * DD);
    float4* __restrict__ o4       = (float4*)(out + ((long)b * MAXLEN + tile0) * DD);

    // j = i*256 + tid, i in [0,12). Incremental f,k: stepping j by 256 with
    // VEC=96 advances f by 2 and k by 64, wrapping k once if k >= 96.
    int f = tid / VEC;           // 0,1,2 (tid<288)
    int k = tid - f * VEC;
    #pragma unroll
    for (int i = 0; i < 12; i++) {
        const int idx = fidx[f];
        float4 val = make_float4(0.f, 0.f, 0.f, 0.f);
        if (idx >= 0) val = __ldg(&x4[idx * VEC + k]);
        __stcs(&o4[f * VEC + k], val);
        // advance by NTHREADS vec4s: +2 frames, +64 lanes (mod 96)
        k += 64; f += 2;
        if (k >= VEC) { k -= VEC; f += 1; }
    }
}

extern "C" void kernel_launch(void* const* d_in, const int* in_sizes, int n_in,
                              void* d_out, int out_size)
{
    const float* x     = (const float*)d_in[0];
    const int*   dur32 = (const int*)d_in[1];
    // d_in[2] = max_len scalar (2048) — shape fixed; hardcoded.

    float* out = (float*)d_out;

    const long main_elems = (long)BB * MAXLEN * DD;       // 25,165,824
    const long tail = (long)out_size - main_elems;

    float*     mel_f32 = nullptr;
    long long* mel_i64 = nullptr;
    if (tail == BB) {
        mel_f32 = out + main_elems;
    } else if (tail == 2 * BB) {
        mel_i64 = (long long*)(out + main_elems);
    }

    lr_index_kernel<<<BB, NTHREADS>>>(dur32, mel_f32, mel_i64);
    dim3 grid(MAXLEN / TILE, BB);   // (64, 32)
    lr_copy_kernel<<<grid, NTHREADS>>>(x, out);
}

// round 6
// speedup vs baseline: 1.1344x; 1.1344x over previous
#include <cuda_runtime.h>
#include <cstdint>

#define BB 32
#define TT 256
#define DD 384
#define MAXLEN 2048
#define TILE 32          // frames per block
#define NTHREADS 256
#define VEC (DD/4)       // 96 float4 per row

__global__ __launch_bounds__(NTHREADS)
void length_regulator_kernel(const float* __restrict__ x,
                             const int* __restrict__ dur32,
                             float* __restrict__ out,
                             float* __restrict__ mel_f32,
                             long long* __restrict__ mel_i64)
{
    __shared__ int csum[TT];
    __shared__ int warpsum[8];
    __shared__ int fidx[TILE];

    const int b     = blockIdx.y;
    const int tile0 = blockIdx.x * TILE;
    const int tid   = threadIdx.x;
    const int lane  = tid & 31;
    const int w     = tid >> 5;

    // ---- dtype layout detection (int32 vs int64 LE): durations in [0,8), so
    // an int64 buffer has every odd 32-bit word of the first 512 words == 0.
    // All blocks probe the same region -> globally consistent decision.
    int probe = dur32[2 * tid + 1];
    const int is64 = (__syncthreads_or(probe) == 0);

    // ---- inclusive scan of 256 durations: warp shuffles + 1 cross-warp pass
    int d = is64 ? dur32[(b * TT + tid) * 2] : dur32[b * TT + tid];
    int s = d;
    #pragma unroll
    for (int off = 1; off < 32; off <<= 1) {
        int t = __shfl_up_sync(0xffffffffu, s, off);
        if (lane >= off) s += t;
    }
    if (lane == 31) warpsum[w] = s;
    __syncthreads();
    if (w == 0 && lane < 8) {
        int ws = warpsum[lane];
        #pragma unroll
        for (int off = 1; off < 8; off <<= 1) {
            int t = __shfl_up_sync(0xffu, ws, off);
            if (lane >= off) ws += t;
        }
        warpsum[lane] = ws;   // inclusive warp sums
    }
    __syncthreads();
    int base = (w > 0) ? warpsum[w - 1] : 0;
    csum[tid] = s + base;
    __syncthreads();
    const int mel_len = csum[TT - 1];

    // ---- frame -> token index: searchsorted-right, 257-value space -> 9 iters
    if (tid < TILE) {
        int t = tile0 + tid;
        if (t >= mel_len) {
            fidx[tid] = -1;
        } else {
            int lo = 0, hi = TT;
            #pragma unroll
            for (int it = 0; it < 9; it++) {
                int mid = (lo + hi) >> 1;
                if (csum[mid] > t) hi = mid; else lo = mid + 1;
            }
            fidx[tid] = (lo < TT - 1) ? lo : (TT - 1);
        }
    }
    if (blockIdx.x == 0 && tid == 0) {
        if (mel_f32) mel_f32[b] = (float)mel_len;
        if (mel_i64) mel_i64[b] = (long long)mel_len;
    }
    __syncthreads();

    // ---- streaming expand: 3072 vec4s per block, 12 per thread,
    //      in two load-all/store-all batches of 6 for MLP.
    const float4* __restrict__ x4 = (const float4*)(x + (long)b * TT * DD);
    float4* __restrict__ o4       = (float4*)(out + ((long)b * MAXLEN + tile0) * DD);

    int f = tid / VEC;            // 0..2
    int k = tid - f * VEC;

    #pragma unroll
    for (int half = 0; half < 2; half++) {
        float4 v[6];
        #pragma unroll
        for (int i = 0; i < 6; i++) {
            const int idx = fidx[f];
            if (idx >= 0) v[i] = __ldg(&x4[idx * VEC + k]);
            else          v[i] = make_float4(0.f, 0.f, 0.f, 0.f);
            // advance by NTHREADS vec4s: +2 frames, +64 lanes (mod 96)
            k += 64; f += 2;
            if (k >= VEC) { k -= VEC; f += 1; }
        }
        #pragma unroll
        for (int i = 0; i < 6; i++) {
            // linear store offset: j = (half*6 + i) * NTHREADS + tid
            __stcs(&o4[(half * 6 + i) * NTHREADS + tid], v[i]);
        }
    }
}

extern "C" void kernel_launch(void* const* d_in, const int* in_sizes, int n_in,
                              void* d_out, int out_size)
{
    const float* x     = (const float*)d_in[0];
    const int*   dur32 = (const int*)d_in[1];
    // d_in[2] = max_len scalar (2048) — shape fixed; hardcoded.

    float* out = (float*)d_out;

    const long main_elems = (long)BB * MAXLEN * DD;       // 25,165,824
    const long tail = (long)out_size - main_elems;

    float*     mel_f32 = nullptr;
    long long* mel_i64 = nullptr;
    if (tail == BB) {
        mel_f32 = out + main_elems;
    } else if (tail == 2 * BB) {
        mel_i64 = (long long*)(out + main_elems);
    }

    dim3 grid(MAXLEN / TILE, BB);   // (64, 32)
    length_regulator_kernel<<<grid, NTHREADS>>>(x, dur32, out, mel_f32, mel_i64);
}